// round 1
// baseline (speedup 1.0000x reference)
#include <cuda_runtime.h>
#include <math_constants.h>

// ---------------- problem constants ----------------
#define BATCH 4
#define NTOK 4096            // 64*64
#define CIN 256
#define ADIM 128
#define MTOT (BATCH*NTOK)    // 16384
#define NEG_SLOPE 0.2f

// ---------------- scratch (no allocations allowed) ----------------
__device__ float g_Q[MTOT * ADIM];
__device__ float g_K[MTOT * ADIM];
__device__ float g_V[MTOT * ADIM];
__device__ float g_O[MTOT * ADIM];

// ---------------- f32x2 packed helpers ----------------
typedef unsigned long long ull;

__device__ __forceinline__ ull pack2(float lo, float hi) {
    ull r; asm("mov.b64 %0, {%1,%2};" : "=l"(r) : "f"(lo), "f"(hi)); return r;
}
__device__ __forceinline__ void unpack2(ull v, float &lo, float &hi) {
    asm("mov.b64 {%0,%1}, %2;" : "=f"(lo), "=f"(hi) : "l"(v));
}
__device__ __forceinline__ ull ffma2(ull a, ull b, ull c) {
    ull d; asm("fma.rn.f32x2 %0, %1, %2, %3;" : "=l"(d) : "l"(a), "l"(b), "l"(c)); return d;
}
__device__ __forceinline__ ull fmul2(ull a, ull b) {
    ull d; asm("mul.rn.f32x2 %0, %1, %2;" : "=l"(d) : "l"(a), "l"(b)); return d;
}

__device__ __forceinline__ float lrelu(float x) {
    return x >= 0.0f ? x : NEG_SLOPE * x;
}

// =====================================================================
// Kernel 1: QKV projection.  Out[m, a] = lrelu(sum_c X[m,c] * W[c,a])
// M=16384, K=256, N=128.  BM=128, BK=64, 256 threads, 8x8 microtile
// (packed as 8 rows x 4 f32x2 column-pairs).
// grid = (128, 1, 3)  z selects Wq/Wk/Wv -> g_Q/g_K/g_V
// smem: Xs[128][66] + Ws[64][128]
// =====================================================================
#define QKV_SMEM ((128*66 + 64*128) * 4)

__global__ __launch_bounds__(256)
void qkv_kernel(const float* __restrict__ X,
                const float* __restrict__ Wq,
                const float* __restrict__ Wk,
                const float* __restrict__ Wv) {
    extern __shared__ float sm[];
    float* Xs = sm;                 // [128][66]
    float* Ws = sm + 128 * 66;      // [64][128]

    const float* Wsel = (blockIdx.z == 0) ? Wq : (blockIdx.z == 1) ? Wk : Wv;
    float* Out = (blockIdx.z == 0) ? g_Q : (blockIdx.z == 1) ? g_K : g_V;

    const int tid = threadIdx.x;
    const int tx = tid & 15;        // 16 col-groups (8 cols each)
    const int ty = tid >> 4;        // 16 row-groups (8 rows each)
    const int row0 = blockIdx.x * 128;

    ull acc[8][4];
    #pragma unroll
    for (int i = 0; i < 8; i++)
        #pragma unroll
        for (int j = 0; j < 4; j++) acc[i][j] = 0ull;

    for (int kc = 0; kc < CIN; kc += 64) {
        // load X tile 128x64 (float4 gmem, 2x float2 smem store: stride 66)
        #pragma unroll
        for (int it = 0; it < 8; it++) {
            int i = tid + it * 256;          // 2048 float4 total
            int r = i >> 4;
            int c = (i & 15) << 2;
            float4 v = *(const float4*)&X[(size_t)(row0 + r) * CIN + kc + c];
            float* d = &Xs[r * 66 + c];
            *(float2*)d = make_float2(v.x, v.y);
            *(float2*)(d + 2) = make_float2(v.z, v.w);
        }
        // load W tile 64x128
        #pragma unroll
        for (int it = 0; it < 8; it++) {
            int i = tid + it * 256;          // 2048 float4 total
            int r = i >> 5;
            int c = (i & 31) << 2;
            *(float4*)&Ws[r * 128 + c] =
                *(const float4*)&Wsel[(size_t)(kc + r) * ADIM + c];
        }
        __syncthreads();

        #pragma unroll 8
        for (int k = 0; k < 64; k++) {
            ull b[4];
            #pragma unroll
            for (int jc = 0; jc < 4; jc++)
                b[jc] = *(const ull*)&Ws[k * 128 + tx * 8 + jc * 2];
            #pragma unroll
            for (int i = 0; i < 8; i++) {
                float a = Xs[(ty * 8 + i) * 66 + k];
                ull a2 = pack2(a, a);
                #pragma unroll
                for (int jc = 0; jc < 4; jc++)
                    acc[i][jc] = ffma2(a2, b[jc], acc[i][jc]);
            }
        }
        __syncthreads();
    }

    // epilogue: leaky relu + store
    #pragma unroll
    for (int i = 0; i < 8; i++) {
        int row = row0 + ty * 8 + i;
        #pragma unroll
        for (int jc = 0; jc < 4; jc++) {
            float lo, hi; unpack2(acc[i][jc], lo, hi);
            lo = lrelu(lo); hi = lrelu(hi);
            *(float2*)&Out[(size_t)row * ADIM + tx * 8 + jc * 2] = make_float2(lo, hi);
        }
    }
}

// =====================================================================
// Kernel 2: flash attention, fp32, no scale.
//   per block: 64 query rows of one batch, loop over 64 KV tiles of 64.
// grid = (64, 4), 256 threads.
// smem: Qs[64][130] | Ks[64][130] (reused as Ps[64][65]) | Vs[64][128]
// Thread map S:  rows ty*4+i (i<4), cols tx*4+j (j<4)
// Thread map O:  rows ty*4+i (i<4), cols tx*8+2*jc (jc<4, f32x2 pairs)
// =====================================================================
#define ATTN_SMEM ((64*130 + 64*130 + 64*128) * 4)

__global__ __launch_bounds__(256)
void attn_kernel() {
    extern __shared__ float sm[];
    float* Qs = sm;                   // [64][130]
    float* Ks = sm + 64 * 130;        // [64][130]
    float* Vs = sm + 2 * 64 * 130;    // [64][128]
    float* Ps = Ks;                   // overlay: P written after S consumed

    const int b = blockIdx.y;
    const int q0 = blockIdx.x * 64;
    const int tid = threadIdx.x;
    const int tx = tid & 15;
    const int ty = tid >> 4;

    const float* Qg = g_Q + (size_t)(b * NTOK + q0) * ADIM;

    // load Q tile 64x128 -> stride 130
    #pragma unroll
    for (int it = 0; it < 16; it++) {
        int i = tid + it * 256;       // 4096 float2 total
        int r = i >> 6;
        int c = (i & 63) << 1;
        *(float2*)&Qs[r * 130 + c] = *(const float2*)&Qg[r * ADIM + c];
    }

    float m[4], l[4];
    ull oacc[4][4];
    #pragma unroll
    for (int i = 0; i < 4; i++) {
        m[i] = -CUDART_INF_F; l[i] = 0.0f;
        #pragma unroll
        for (int jc = 0; jc < 4; jc++) oacc[i][jc] = 0ull;
    }

    for (int t = 0; t < 64; t++) {
        __syncthreads();   // previous PV done reading Vs / Ps(=Ks)
        const float* Kg = g_K + (size_t)(b * NTOK + t * 64) * ADIM;
        const float* Vg = g_V + (size_t)(b * NTOK + t * 64) * ADIM;
        #pragma unroll
        for (int it = 0; it < 16; it++) {
            int i = tid + it * 256;
            int r = i >> 6;
            int c = (i & 63) << 1;
            *(float2*)&Ks[r * 130 + c] = *(const float2*)&Kg[r * ADIM + c];
            *(float2*)&Vs[r * 128 + c] = *(const float2*)&Vg[r * ADIM + c];
        }
        __syncthreads();

        // ---- S = Q K^T (pack over k) ----
        ull sa[4][4];
        #pragma unroll
        for (int i = 0; i < 4; i++)
            #pragma unroll
            for (int j = 0; j < 4; j++) sa[i][j] = 0ull;

        const float* qbase = &Qs[(ty * 4) * 130];
        const float* kbase = &Ks[(tx * 4) * 130];
        #pragma unroll 8
        for (int kp = 0; kp < 64; kp++) {
            ull qv[4], kv[4];
            #pragma unroll
            for (int i = 0; i < 4; i++)
                qv[i] = *(const ull*)&qbase[i * 130 + kp * 2];
            #pragma unroll
            for (int j = 0; j < 4; j++)
                kv[j] = *(const ull*)&kbase[j * 130 + kp * 2];
            #pragma unroll
            for (int i = 0; i < 4; i++)
                #pragma unroll
                for (int j = 0; j < 4; j++)
                    sa[i][j] = ffma2(qv[i], kv[j], sa[i][j]);
        }
        float s[4][4];
        #pragma unroll
        for (int i = 0; i < 4; i++)
            #pragma unroll
            for (int j = 0; j < 4; j++) {
                float lo, hi; unpack2(sa[i][j], lo, hi);
                s[i][j] = lo + hi;
            }

        __syncthreads();   // all Ks reads done before Ps overlay writes

        // ---- online softmax (row groups: each row lives in 16 lanes) ----
        #pragma unroll
        for (int i = 0; i < 4; i++) {
            float mx = fmaxf(fmaxf(s[i][0], s[i][1]), fmaxf(s[i][2], s[i][3]));
            #pragma unroll
            for (int off = 8; off >= 1; off >>= 1)
                mx = fmaxf(mx, __shfl_xor_sync(0xffffffffu, mx, off));
            float mnew = fmaxf(m[i], mx);
            float sum = 0.0f;
            int prow = (ty * 4 + i) * 65;
            #pragma unroll
            for (int j = 0; j < 4; j++) {
                float p = __expf(s[i][j] - mnew);
                sum += p;
                Ps[prow + tx * 4 + j] = p;
            }
            #pragma unroll
            for (int off = 8; off >= 1; off >>= 1)
                sum += __shfl_xor_sync(0xffffffffu, sum, off);
            float sc = __expf(m[i] - mnew);
            l[i] = l[i] * sc + sum;
            m[i] = mnew;
            ull sc2 = pack2(sc, sc);
            #pragma unroll
            for (int jc = 0; jc < 4; jc++)
                oacc[i][jc] = fmul2(oacc[i][jc], sc2);
        }
        __syncthreads();   // Ps visible to all

        // ---- O += P V (pack over output cols) ----
        const float* pbase = &Ps[(ty * 4) * 65];
        const float* vbase = &Vs[tx * 8];
        #pragma unroll 8
        for (int jp = 0; jp < 64; jp++) {
            ull vv[4];
            #pragma unroll
            for (int jc = 0; jc < 4; jc++)
                vv[jc] = *(const ull*)&vbase[jp * 128 + jc * 2];
            #pragma unroll
            for (int i = 0; i < 4; i++) {
                float p = pbase[i * 65 + jp];
                ull p2 = pack2(p, p);
                #pragma unroll
                for (int jc = 0; jc < 4; jc++)
                    oacc[i][jc] = ffma2(p2, vv[jc], oacc[i][jc]);
            }
        }
    }

    // epilogue: divide by l, store O
    float* Og = g_O + (size_t)(b * NTOK + q0) * ADIM;
    #pragma unroll
    for (int i = 0; i < 4; i++) {
        float inv = 1.0f / l[i];
        int row = ty * 4 + i;
        #pragma unroll
        for (int jc = 0; jc < 4; jc++) {
            float lo, hi; unpack2(oacc[i][jc], lo, hi);
            *(float2*)&Og[(size_t)row * ADIM + tx * 8 + jc * 2] =
                make_float2(lo * inv, hi * inv);
        }
    }
}

// =====================================================================
// Kernel 3: Y = O @ Wo, then * tanh(relu(1 + w_gamma[c])).
// M=16384, K=128, N=256.  BM=128, BN=128, BK=64, grid (128, 2).
// smem: Os[128][66] + Ws[64][128]
// =====================================================================
#define OUT_SMEM ((128*66 + 64*128) * 4)

__global__ __launch_bounds__(256)
void out_kernel(const float* __restrict__ Wo,
                const float* __restrict__ wg,
                float* __restrict__ Y) {
    extern __shared__ float sm[];
    float* Os = sm;                 // [128][66]
    float* Ws = sm + 128 * 66;      // [64][128]

    const int tid = threadIdx.x;
    const int tx = tid & 15;
    const int ty = tid >> 4;
    const int row0 = blockIdx.x * 128;
    const int col0 = blockIdx.y * 128;

    ull acc[8][4];
    #pragma unroll
    for (int i = 0; i < 8; i++)
        #pragma unroll
        for (int j = 0; j < 4; j++) acc[i][j] = 0ull;

    for (int kc = 0; kc < ADIM; kc += 64) {
        #pragma unroll
        for (int it = 0; it < 8; it++) {
            int i = tid + it * 256;
            int r = i >> 4;
            int c = (i & 15) << 2;
            float4 v = *(const float4*)&g_O[(size_t)(row0 + r) * ADIM + kc + c];
            float* d = &Os[r * 66 + c];
            *(float2*)d = make_float2(v.x, v.y);
            *(float2*)(d + 2) = make_float2(v.z, v.w);
        }
        #pragma unroll
        for (int it = 0; it < 8; it++) {
            int i = tid + it * 256;
            int r = i >> 5;
            int c = (i & 31) << 2;
            *(float4*)&Ws[r * 128 + c] =
                *(const float4*)&Wo[(size_t)(kc + r) * CIN + col0 + c];
        }
        __syncthreads();

        #pragma unroll 8
        for (int k = 0; k < 64; k++) {
            ull b[4];
            #pragma unroll
            for (int jc = 0; jc < 4; jc++)
                b[jc] = *(const ull*)&Ws[k * 128 + tx * 8 + jc * 2];
            #pragma unroll
            for (int i = 0; i < 8; i++) {
                float a = Os[(ty * 8 + i) * 66 + k];
                ull a2 = pack2(a, a);
                #pragma unroll
                for (int jc = 0; jc < 4; jc++)
                    acc[i][jc] = ffma2(a2, b[jc], acc[i][jc]);
            }
        }
        __syncthreads();
    }

    // epilogue: gamma scale + store
    float gam[8];
    #pragma unroll
    for (int jj = 0; jj < 8; jj++) {
        int c = col0 + tx * 8 + jj;
        gam[jj] = tanhf(fmaxf(1.0f + wg[c], 0.0f));
    }
    #pragma unroll
    for (int i = 0; i < 8; i++) {
        int row = row0 + ty * 8 + i;
        #pragma unroll
        for (int jc = 0; jc < 4; jc++) {
            float lo, hi; unpack2(acc[i][jc], lo, hi);
            lo *= gam[jc * 2]; hi *= gam[jc * 2 + 1];
            *(float2*)&Y[(size_t)row * CIN + col0 + tx * 8 + jc * 2] =
                make_float2(lo, hi);
        }
    }
}

// =====================================================================
extern "C" void kernel_launch(void* const* d_in, const int* in_sizes, int n_in,
                              void* d_out, int out_size) {
    const float* x  = (const float*)d_in[0];
    const float* Wq = (const float*)d_in[1];
    const float* Wk = (const float*)d_in[2];
    const float* Wv = (const float*)d_in[3];
    const float* Wo = (const float*)d_in[4];
    const float* wg = (const float*)d_in[5];
    float* y = (float*)d_out;

    static bool attrs_set = []() {
        cudaFuncSetAttribute(qkv_kernel, cudaFuncAttributeMaxDynamicSharedMemorySize, QKV_SMEM);
        cudaFuncSetAttribute(attn_kernel, cudaFuncAttributeMaxDynamicSharedMemorySize, ATTN_SMEM);
        cudaFuncSetAttribute(out_kernel, cudaFuncAttributeMaxDynamicSharedMemorySize, OUT_SMEM);
        return true;
    }();
    (void)attrs_set;

    qkv_kernel<<<dim3(MTOT / 128, 1, 3), 256, QKV_SMEM>>>(x, Wq, Wk, Wv);
    attn_kernel<<<dim3(NTOK / 64, BATCH), 256, ATTN_SMEM>>>();
    out_kernel<<<dim3(MTOT / 128, CIN / 128), 256, OUT_SMEM>>>(Wo, wg, y);
}